// round 8
// baseline (speedup 1.0000x reference)
#include <cuda_runtime.h>
#include <cuda_bf16.h>
#include <cstdint>

#define B_    2
#define CIN_  256
#define COUT_ 256
#define H_    128
#define W_    128
#define HW_   (H_*W_)
#define KK_   3
#define G_    4
#define OCH_  (G_*2*KK_*KK_)   // 72
#define KRED  (CIN_*KK_*KK_)   // 2304
#define NCHUNK (G_*KK_*KK_)    // 36 chunks of 64 k each
#define NPB   (B_*HW_/128)     // 256 pixel tiles

// Scratch buffers
__device__ float g_offset[B_*HW_*OCH_];                  // [pix][72]
__device__ float g_xt[(size_t)B_*HW_*CIN_];              // NHWC: [b][hw][c]
__device__ __nv_bfloat16 g_wb[(size_t)NCHUNK*2*256*64];  // per chunk: [hi 32KB][lo 32KB] swizzled [n][k]
// Sampled A tiles, SW128-swizzled, 16KB per (chunk, pixtile): [gt][pb][128p][64k]
__device__ __nv_bfloat16 g_ah[(size_t)NCHUNK*NPB*128*64];
__device__ __nv_bfloat16 g_al[(size_t)NCHUNK*NPB*128*64];

// ---------------------------------------------------------------------------
// helpers
// ---------------------------------------------------------------------------
__device__ __forceinline__ uint32_t smem_u32(const void* p) {
    uint32_t a;
    asm("{ .reg .u64 t; cvta.to.shared.u64 t, %1; cvt.u32.u64 %0, t; }" : "=r"(a) : "l"(p));
    return a;
}
__device__ __forceinline__ void ldsm_x4(uint32_t r[4], uint32_t addr) {
    asm volatile("ldmatrix.sync.aligned.m8n8.x4.shared.b16 {%0,%1,%2,%3}, [%4];"
                 : "=r"(r[0]), "=r"(r[1]), "=r"(r[2]), "=r"(r[3]) : "r"(addr));
}
__device__ __forceinline__ void mma_bf16(float d[4], const uint32_t a[4],
                                         uint32_t b0, uint32_t b1) {
    asm volatile(
        "mma.sync.aligned.m16n8k16.row.col.f32.bf16.bf16.f32 "
        "{%0,%1,%2,%3}, {%4,%5,%6,%7}, {%8,%9}, {%0,%1,%2,%3};"
        : "+f"(d[0]), "+f"(d[1]), "+f"(d[2]), "+f"(d[3])
        : "r"(a[0]), "r"(a[1]), "r"(a[2]), "r"(a[3]), "r"(b0), "r"(b1));
}
__device__ __forceinline__ void mbar_init(uint32_t mbar, uint32_t cnt) {
    asm volatile("mbarrier.init.shared.b64 [%0], %1;" :: "r"(mbar), "r"(cnt) : "memory");
}
__device__ __forceinline__ void mbar_arrive(uint32_t mbar) {
    asm volatile("mbarrier.arrive.shared.b64 _, [%0];" :: "r"(mbar) : "memory");
}
__device__ __forceinline__ void mbar_expect_tx(uint32_t mbar, uint32_t bytes) {
    asm volatile("mbarrier.arrive.expect_tx.shared.b64 _, [%0], %1;"
                 :: "r"(mbar), "r"(bytes) : "memory");
}
__device__ __forceinline__ void mbar_wait(uint32_t mbar, uint32_t parity) {
    asm volatile(
        "{\n\t.reg .pred P;\n\t"
        "WL_%=:\n\t"
        "mbarrier.try_wait.parity.acquire.cta.shared::cta.b64 P, [%0], %1, 0x989680;\n\t"
        "@P bra.uni WD_%=;\n\t"
        "bra.uni WL_%=;\n\t"
        "WD_%=:\n\t}"
        :: "r"(mbar), "r"(parity) : "memory");
}
__device__ __forceinline__ void bulk_copy(uint32_t dst, const void* src, uint32_t bytes,
                                          uint32_t mbar) {
    asm volatile(
        "cp.async.bulk.shared::cta.global.mbarrier::complete_tx::bytes [%0], [%1], %2, [%3];"
        :: "r"(dst), "l"(src), "r"(bytes), "r"(mbar) : "memory");
}

// ---------------------------------------------------------------------------
// Kernel A: NCHW -> NHWC transpose (32x32 tiles)
// ---------------------------------------------------------------------------
__global__ void __launch_bounds__(256) transpose_kernel(const float* __restrict__ x,
                                                        float* __restrict__ xt)
{
    __shared__ float tl[32][33];
    const int tx = threadIdx.x, ty = threadIdx.y;
    const int bb = blockIdx.z;
    const int hw0 = blockIdx.x * 32;
    const int c0  = blockIdx.y * 32;
#pragma unroll
    for (int r = 0; r < 4; r++)
        tl[ty + 8*r][tx] = x[((size_t)bb*CIN_ + c0 + ty + 8*r)*HW_ + hw0 + tx];
    __syncthreads();
#pragma unroll
    for (int r = 0; r < 4; r++)
        xt[((size_t)bb*HW_ + hw0 + ty + 8*r)*CIN_ + c0 + tx] = tl[tx][ty + 8*r];
}

// ---------------------------------------------------------------------------
// Kernel B: weight prepack -> bf16 hi/lo, [n][k] tiles, SW128 swizzled.
// ---------------------------------------------------------------------------
__global__ void __launch_bounds__(256) prepack_kernel(const float* __restrict__ wd,
                                                      __nv_bfloat16* __restrict__ wb)
{
    const int gt = blockIdx.x;
    const int g = gt / 9;
    const int tap = gt - 9*g;
    for (int idx = threadIdx.x; idx < 256*64; idx += 256) {
        const int n  = idx >> 6;
        const int cg = idx & 63;
        float v = wd[(size_t)n*KRED + (g*64 + cg)*9 + tap];
        __nv_bfloat16 h = __float2bfloat16_rn(v);
        __nv_bfloat16 l = __float2bfloat16_rn(v - __bfloat162float(h));
        const int dst = n*64 + (cg ^ ((n & 7) << 3));   // SW128 (bf16 elems)
        wb[(size_t)gt*32768 + dst]          = h;
        wb[(size_t)gt*32768 + 16384 + dst]  = l;
    }
}

// ---------------------------------------------------------------------------
// Kernel C: 1x1 offset conv (fp32)
// ---------------------------------------------------------------------------
__global__ void __launch_bounds__(256) offset_kernel(
    const float* __restrict__ x,
    const float* __restrict__ w,
    const float* __restrict__ bias)
{
    __shared__ float xs[16][64];
    __shared__ float ws[72][16];

    const int t    = threadIdx.x;
    const int pix0 = blockIdx.x * 64;
    const int b    = pix0 >> 14;
    const int rem  = pix0 & (HW_-1);
    const int hh   = rem >> 7;
    const int w0   = rem & (W_-1);

    const int p  = t & 63;
    const int oq = t >> 6;

    float acc[18];
#pragma unroll
    for (int i = 0; i < 18; i++) acc[i] = 0.f;

    const float* xbase = x + (size_t)b * CIN_ * HW_ + hh * W_ + w0;

    for (int c0 = 0; c0 < CIN_; c0 += 16) {
#pragma unroll
        for (int r = 0; r < 4; r++) {
            int e  = t + r * 256;
            int kk = e >> 6;
            int pp = e & 63;
            xs[kk][pp] = xbase[(size_t)(c0 + kk) * HW_ + pp];
        }
        for (int e = t; e < 72 * 16; e += 256) {
            int o  = e >> 4;
            int kk = e & 15;
            ws[o][kk] = w[o * CIN_ + c0 + kk];
        }
        __syncthreads();
#pragma unroll
        for (int kk = 0; kk < 16; kk++) {
            float xv = xs[kk][p];
#pragma unroll
            for (int i = 0; i < 18; i++)
                acc[i] = fmaf(xv, ws[oq * 18 + i][kk], acc[i]);
        }
        __syncthreads();
    }

    float* ob = g_offset + (size_t)(pix0 + p) * OCH_;
#pragma unroll
    for (int i = 0; i < 18; i++) {
        int o = oq * 18 + i;
        ob[o] = acc[i] + bias[o];
    }
}

// ---------------------------------------------------------------------------
// Kernel D: sampler — bilinear gather + bf16 hi/lo split, writes SW128
// swizzled 16KB A-tiles to gmem. grid = (256 pixtiles, 36 chunks), 256 thr.
// ---------------------------------------------------------------------------
__global__ void __launch_bounds__(256) sample_kernel(const float* __restrict__ xt)
{
    __shared__ int   sidx[4*128];
    __shared__ float swgt[4*128];

    const int t  = threadIdx.x;
    const int pb = blockIdx.x;       // pixel tile
    const int gt = blockIdx.y;       // chunk
    const int pix0 = pb * 128;
    const int b    = pix0 >> 14;
    const int hw0  = pix0 & (HW_-1);
    const int hh   = hw0 >> 7;

    const int g   = gt / 9;
    const int tap = gt - 9*g;
    const int ti  = tap / 3;
    const int tj  = tap - 3*ti;
    const int gch = g * 64;

    if (t < 128) {
        const float* op = g_offset + (size_t)(pix0 + t) * OCH_ + gt*2;
        float ys = (float)(hh - 1 + ti) + op[0];
        float xs = (float)(t  - 1 + tj) + op[1];
        float y0f = floorf(ys), x0f = floorf(xs);
        int   y0  = (int)y0f,   x0  = (int)x0f;
        float ly = ys - y0f, lx = xs - x0f;
        float hy = 1.f - ly, hx = 1.f - lx;
        int y1 = y0 + 1, x1 = x0 + 1;
        bool vy0 = (unsigned)y0 < H_, vy1 = (unsigned)y1 < H_;
        bool vx0 = (unsigned)x0 < W_, vx1 = (unsigned)x1 < W_;
        int cy0 = min(max(y0,0),H_-1), cy1 = min(max(y1,0),H_-1);
        int cx0 = min(max(x0,0),W_-1), cx1 = min(max(x1,0),W_-1);
        sidx[0*128 + t] = cy0*W_ + cx0;
        sidx[1*128 + t] = cy0*W_ + cx1;
        sidx[2*128 + t] = cy1*W_ + cx0;
        sidx[3*128 + t] = cy1*W_ + cx1;
        swgt[0*128 + t] = (vy0 && vx0) ? hy*hx : 0.f;
        swgt[1*128 + t] = (vy0 && vx1) ? hy*lx : 0.f;
        swgt[2*128 + t] = (vy1 && vx0) ? ly*hx : 0.f;
        swgt[3*128 + t] = (vy1 && vx1) ? ly*lx : 0.f;
    }
    __syncthreads();

    const float* xb = xt + (size_t)b * HW_ * CIN_;
    const int slot = t & 15;
    const int gp   = t >> 4;

    char* outh = (char*)g_ah + ((size_t)gt*NPB + pb) * 16384;
    char* outl = (char*)g_al + ((size_t)gt*NPB + pb) * 16384;

#pragma unroll
    for (int pass = 0; pass < 8; pass++) {
        const int p  = pass*16 + gp;
        const int i0 = sidx[0*128+p], i1 = sidx[1*128+p];
        const int i2 = sidx[2*128+p], i3 = sidx[3*128+p];
        const float w0 = swgt[0*128+p], w1 = swgt[1*128+p];
        const float w2 = swgt[2*128+p], w3 = swgt[3*128+p];
        const int co = gch + slot*4;
        float4 v0 = *(const float4*)(xb + (size_t)i0*CIN_ + co);
        float4 v1 = *(const float4*)(xb + (size_t)i1*CIN_ + co);
        float4 v2 = *(const float4*)(xb + (size_t)i2*CIN_ + co);
        float4 v3 = *(const float4*)(xb + (size_t)i3*CIN_ + co);
        float r0 = fmaf(w3,v3.x, fmaf(w2,v2.x, fmaf(w1,v1.x, w0*v0.x)));
        float r1 = fmaf(w3,v3.y, fmaf(w2,v2.y, fmaf(w1,v1.y, w0*v0.y)));
        float r2 = fmaf(w3,v3.z, fmaf(w2,v2.z, fmaf(w1,v1.z, w0*v0.z)));
        float r3 = fmaf(w3,v3.w, fmaf(w2,v2.w, fmaf(w1,v1.w, w0*v0.w)));

        __nv_bfloat16 h0 = __float2bfloat16_rn(r0);
        __nv_bfloat16 h1 = __float2bfloat16_rn(r1);
        __nv_bfloat16 h2 = __float2bfloat16_rn(r2);
        __nv_bfloat16 h3 = __float2bfloat16_rn(r3);
        __nv_bfloat16 l0 = __float2bfloat16_rn(r0 - __bfloat162float(h0));
        __nv_bfloat16 l1 = __float2bfloat16_rn(r1 - __bfloat162float(h1));
        __nv_bfloat16 l2 = __float2bfloat16_rn(r2 - __bfloat162float(h2));
        __nv_bfloat16 l3 = __float2bfloat16_rn(r3 - __bfloat162float(h3));

        const uint32_t off = (uint32_t)(p*128 + ((slot*8) ^ ((p & 7) << 4)));
        __nv_bfloat162 hA(h0, h1), hB(h2, h3), lA(l0, l1), lB(l2, l3);
        uint2 hv, lv;
        hv.x = *(uint32_t*)&hA; hv.y = *(uint32_t*)&hB;
        lv.x = *(uint32_t*)&lA; lv.y = *(uint32_t*)&lB;
        *(uint2*)(outh + off) = hv;
        *(uint2*)(outl + off) = lv;
    }
}

// ---------------------------------------------------------------------------
// Kernel E: pure GEMM on HMMA, loads via cp.async.bulk + mbarrier.
// 128 pix x 256 cout per block, 512 threads (16 warps = 4m x 4n, warp 32x64).
// 2-stage producer/consumer pipeline with full/empty mbarriers; NO
// __syncthreads in the mainloop — warps decouple elastically by one chunk.
// Stage = Ah 16K | Al 16K | Bh 32K | Bl 32K = 96KB.
// ---------------------------------------------------------------------------
#define GS_AH 0
#define GS_AL 16384
#define GS_BH 32768
#define GS_BL 65536
#define GSTAGE 98304
#define GS_FULL (2*GSTAGE)          // full[0], full[1] (8B each)
#define GS_EMPTY (2*GSTAGE + 16)    // empty[0], empty[1]
#define GSMEM (2*GSTAGE + 64)

__device__ __forceinline__ void gemm_issue_bulk(uint32_t sbase, uint32_t mbar,
                                                int gt, int pb,
                                                const __nv_bfloat16* wb)
{
    const char* ah = (const char*)g_ah + ((size_t)gt*NPB + pb) * 16384;
    const char* al = (const char*)g_al + ((size_t)gt*NPB + pb) * 16384;
    const char* bs = (const char*)wb + (size_t)gt * 65536;
    mbar_expect_tx(mbar, GSTAGE);
    bulk_copy(sbase + GS_AH, ah, 16384, mbar);
    bulk_copy(sbase + GS_AL, al, 16384, mbar);
    bulk_copy(sbase + GS_BH, bs, 65536, mbar);   // hi+lo contiguous in g_wb
}

__global__ void __launch_bounds__(512, 1)
gemm_kernel(const __nv_bfloat16* __restrict__ wb, float* __restrict__ out)
{
    extern __shared__ char sm[];
    const uint32_t sb = smem_u32(sm);

    const int t = threadIdx.x;
    const int warp = t >> 5, lane = t & 31;
    const int pb   = blockIdx.x;
    const int pix0 = pb * 128;
    const int b    = pix0 >> 14;
    const int hw0  = pix0 & (HW_-1);

    // mbarrier init: full = tx-based (count 1), empty = 16 warp arrivals
    if (t == 0) {
        mbar_init(sb + GS_FULL, 1);
        mbar_init(sb + GS_FULL + 8, 1);
        mbar_init(sb + GS_EMPTY, 16);
        mbar_init(sb + GS_EMPTY + 8, 16);
    }
    __syncthreads();

    if (t == 0) {
        gemm_issue_bulk(sb,          sb + GS_FULL,     0, pb, wb);
        gemm_issue_bulk(sb + GSTAGE, sb + GS_FULL + 8, 1, pb, wb);
    }

    const int wm = warp & 3, wn = warp >> 2;

    const uint32_t rowA = wm*32 + (lane & 15);
    const uint32_t swzA = (rowA & 7) << 4;
    const uint32_t kA   = (uint32_t)(lane & 16);
    const uint32_t aRow = rowA * 128;

    const uint32_t rowB = wn*64 + (lane & 7) + ((lane & 16) >> 1);
    const uint32_t swzB = (rowB & 7) << 4;
    const uint32_t kB   = (uint32_t)((lane & 8) << 1);
    const uint32_t bRow = rowB * 128;

    float acc[2][8][4];
#pragma unroll
    for (int i = 0; i < 2; i++)
#pragma unroll
        for (int j = 0; j < 8; j++)
#pragma unroll
            for (int q = 0; q < 4; q++) acc[i][j][q] = 0.f;

    for (int gt = 0; gt < NCHUNK; gt++) {
        const int s  = gt & 1;
        const int ph = (gt >> 1) & 1;
        const uint32_t cur = sb + s * GSTAGE;

        mbar_wait(sb + GS_FULL + s * 8, ph);

        // 3 split terms x 4 k-steps of k16
#pragma unroll
        for (int term = 0; term < 3; term++) {
            const uint32_t aBase = cur + (term == 2 ? GS_AL : GS_AH) + aRow;
            const uint32_t bBase = cur + (term == 1 ? GS_BL : GS_BH) + bRow;
#pragma unroll
            for (int ks = 0; ks < 4; ks++) {
                const uint32_t kbyte = (uint32_t)(ks * 32);
                uint32_t a[2][4], bf[4][4];
#pragma unroll
                for (int mt = 0; mt < 2; mt++)
                    ldsm_x4(a[mt], aBase + mt*2048 + ((kbyte + kA) ^ swzA));
#pragma unroll
                for (int np = 0; np < 4; np++)
                    ldsm_x4(bf[np], bBase + np*2048 + ((kbyte + kB) ^ swzB));
#pragma unroll
                for (int mt = 0; mt < 2; mt++)
#pragma unroll
                    for (int nt = 0; nt < 8; nt++)
                        mma_bf16(acc[mt][nt], a[mt],
                                 bf[nt >> 1][(nt & 1) * 2],
                                 bf[nt >> 1][(nt & 1) * 2 + 1]);
            }
        }

        // signal this warp is done with stage s
        if (lane == 0) mbar_arrive(sb + GS_EMPTY + s * 8);

        // producer: refill stage s with chunk gt+2 once all warps are done
        if (t == 0 && gt + 2 < NCHUNK) {
            mbar_wait(sb + GS_EMPTY + s * 8, ph);
            gemm_issue_bulk(cur, sb + GS_FULL + s * 8, gt + 2, pb, wb);
        }
    }

    // ---- epilogue: relu + store (NCHW) ----
    const size_t ob = (size_t)b * COUT_ * HW_ + hw0;
    const int mrow = wm*32 + (lane >> 2);
    const int ncol = wn*64 + (lane & 3) * 2;
#pragma unroll
    for (int mt = 0; mt < 2; mt++) {
#pragma unroll
        for (int nt = 0; nt < 8; nt++) {
            const int m = mrow + mt*16;
            const int n = ncol + nt*8;
            float* o0 = out + ob + (size_t)n * HW_ + m;
            o0[0]        = fmaxf(acc[mt][nt][0], 0.f);
            o0[HW_]      = fmaxf(acc[mt][nt][1], 0.f);
            o0[8]        = fmaxf(acc[mt][nt][2], 0.f);
            o0[HW_ + 8]  = fmaxf(acc[mt][nt][3], 0.f);
        }
    }
}

// ---------------------------------------------------------------------------
extern "C" void kernel_launch(void* const* d_in, const int* in_sizes, int n_in,
                              void* d_out, int out_size)
{
    (void)in_sizes; (void)n_in; (void)out_size;
    const float* x     = (const float*)d_in[0];
    const float* w_off = (const float*)d_in[1];
    const float* b_off = (const float*)d_in[2];
    const float* w_def = (const float*)d_in[3];
    float* out = (float*)d_out;

    float* xt;           cudaGetSymbolAddress((void**)&xt, g_xt);
    __nv_bfloat16* wbp;  cudaGetSymbolAddress((void**)&wbp, g_wb);

    transpose_kernel<<<dim3(HW_/32, CIN_/32, B_), dim3(32, 8)>>>(x, xt);
    prepack_kernel<<<NCHUNK, 256>>>(w_def, wbp);
    offset_kernel<<<B_*HW_/64, 256>>>(x, w_off, b_off);
    sample_kernel<<<dim3(NPB, NCHUNK), 256>>>(xt);

    static bool attr_set = false;
    if (!attr_set) {
        cudaFuncSetAttribute(gemm_kernel,
                             cudaFuncAttributeMaxDynamicSharedMemorySize, GSMEM);
        attr_set = true;
    }
    gemm_kernel<<<NPB, 512, GSMEM>>>(wbp, out);
}

// round 9
// speedup vs baseline: 1.6564x; 1.6564x over previous
#include <cuda_runtime.h>
#include <cuda_bf16.h>
#include <cstdint>

#define B_    2
#define CIN_  256
#define COUT_ 256
#define H_    128
#define W_    128
#define HW_   (H_*W_)
#define KK_   3
#define G_    4
#define OCH_  (G_*2*KK_*KK_)   // 72
#define KRED  (CIN_*KK_*KK_)   // 2304
#define NCHUNK (G_*KK_*KK_)    // 36 chunks of 64 k each
#define NPB   (B_*HW_/128)     // 256 pixel tiles

// Scratch buffers
__device__ float g_offset[B_*HW_*OCH_];                  // [pix][72]
__device__ float g_xt[(size_t)B_*HW_*CIN_];              // NHWC: [b][hw][c]
__device__ __nv_bfloat16 g_wb[(size_t)NCHUNK*2*256*64];  // per chunk: [hi 32KB][lo 32KB] swizzled [n][k]
// Sampled A tiles, SW128-swizzled, 16KB per (chunk, pixtile): [gt][pb][128p][64k]
__device__ __nv_bfloat16 g_ah[(size_t)NCHUNK*NPB*128*64];
__device__ __nv_bfloat16 g_al[(size_t)NCHUNK*NPB*128*64];

// ---------------------------------------------------------------------------
// helpers
// ---------------------------------------------------------------------------
__device__ __forceinline__ uint32_t smem_u32(const void* p) {
    uint32_t a;
    asm("{ .reg .u64 t; cvta.to.shared.u64 t, %1; cvt.u32.u64 %0, t; }" : "=r"(a) : "l"(p));
    return a;
}
__device__ __forceinline__ void ldsm_x4(uint32_t r[4], uint32_t addr) {
    asm volatile("ldmatrix.sync.aligned.m8n8.x4.shared.b16 {%0,%1,%2,%3}, [%4];"
                 : "=r"(r[0]), "=r"(r[1]), "=r"(r[2]), "=r"(r[3]) : "r"(addr));
}
__device__ __forceinline__ void mma_bf16(float d[4], const uint32_t a[4],
                                         uint32_t b0, uint32_t b1) {
    asm volatile(
        "mma.sync.aligned.m16n8k16.row.col.f32.bf16.bf16.f32 "
        "{%0,%1,%2,%3}, {%4,%5,%6,%7}, {%8,%9}, {%0,%1,%2,%3};"
        : "+f"(d[0]), "+f"(d[1]), "+f"(d[2]), "+f"(d[3])
        : "r"(a[0]), "r"(a[1]), "r"(a[2]), "r"(a[3]), "r"(b0), "r"(b1));
}
__device__ __forceinline__ void mbar_init(uint32_t mbar, uint32_t cnt) {
    asm volatile("mbarrier.init.shared.b64 [%0], %1;" :: "r"(mbar), "r"(cnt) : "memory");
}
__device__ __forceinline__ void mbar_expect_tx(uint32_t mbar, uint32_t bytes) {
    asm volatile("mbarrier.arrive.expect_tx.shared.b64 _, [%0], %1;"
                 :: "r"(mbar), "r"(bytes) : "memory");
}
__device__ __forceinline__ void mbar_wait(uint32_t mbar, uint32_t parity) {
    asm volatile(
        "{\n\t.reg .pred P;\n\t"
        "WL_%=:\n\t"
        "mbarrier.try_wait.parity.acquire.cta.shared::cta.b64 P, [%0], %1, 0x989680;\n\t"
        "@P bra.uni WD_%=;\n\t"
        "bra.uni WL_%=;\n\t"
        "WD_%=:\n\t}"
        :: "r"(mbar), "r"(parity) : "memory");
}
__device__ __forceinline__ void bulk_copy(uint32_t dst, const void* src, uint32_t bytes,
                                          uint32_t mbar) {
    asm volatile(
        "cp.async.bulk.shared::cta.global.mbarrier::complete_tx::bytes [%0], [%1], %2, [%3];"
        :: "r"(dst), "l"(src), "r"(bytes), "r"(mbar) : "memory");
}

// ---------------------------------------------------------------------------
// Kernel A: NCHW -> NHWC transpose (32x32 tiles)
// ---------------------------------------------------------------------------
__global__ void __launch_bounds__(256) transpose_kernel(const float* __restrict__ x,
                                                        float* __restrict__ xt)
{
    __shared__ float tl[32][33];
    const int tx = threadIdx.x, ty = threadIdx.y;
    const int bb = blockIdx.z;
    const int hw0 = blockIdx.x * 32;
    const int c0  = blockIdx.y * 32;
#pragma unroll
    for (int r = 0; r < 4; r++)
        tl[ty + 8*r][tx] = x[((size_t)bb*CIN_ + c0 + ty + 8*r)*HW_ + hw0 + tx];
    __syncthreads();
#pragma unroll
    for (int r = 0; r < 4; r++)
        xt[((size_t)bb*HW_ + hw0 + ty + 8*r)*CIN_ + c0 + tx] = tl[tx][ty + 8*r];
}

// ---------------------------------------------------------------------------
// Kernel B: weight prepack -> bf16 hi/lo, [n][k] tiles, SW128 swizzled.
// ---------------------------------------------------------------------------
__global__ void __launch_bounds__(256) prepack_kernel(const float* __restrict__ wd,
                                                      __nv_bfloat16* __restrict__ wb)
{
    const int gt = blockIdx.x;
    const int g = gt / 9;
    const int tap = gt - 9*g;
    for (int idx = threadIdx.x; idx < 256*64; idx += 256) {
        const int n  = idx >> 6;
        const int cg = idx & 63;
        float v = wd[(size_t)n*KRED + (g*64 + cg)*9 + tap];
        __nv_bfloat16 h = __float2bfloat16_rn(v);
        __nv_bfloat16 l = __float2bfloat16_rn(v - __bfloat162float(h));
        const int dst = n*64 + (cg ^ ((n & 7) << 3));   // SW128 (bf16 elems)
        wb[(size_t)gt*32768 + dst]          = h;
        wb[(size_t)gt*32768 + 16384 + dst]  = l;
    }
}

// ---------------------------------------------------------------------------
// Kernel C: 1x1 offset conv (fp32)
// ---------------------------------------------------------------------------
__global__ void __launch_bounds__(256) offset_kernel(
    const float* __restrict__ x,
    const float* __restrict__ w,
    const float* __restrict__ bias)
{
    __shared__ float xs[16][64];
    __shared__ float ws[72][16];

    const int t    = threadIdx.x;
    const int pix0 = blockIdx.x * 64;
    const int b    = pix0 >> 14;
    const int rem  = pix0 & (HW_-1);
    const int hh   = rem >> 7;
    const int w0   = rem & (W_-1);

    const int p  = t & 63;
    const int oq = t >> 6;

    float acc[18];
#pragma unroll
    for (int i = 0; i < 18; i++) acc[i] = 0.f;

    const float* xbase = x + (size_t)b * CIN_ * HW_ + hh * W_ + w0;

    for (int c0 = 0; c0 < CIN_; c0 += 16) {
#pragma unroll
        for (int r = 0; r < 4; r++) {
            int e  = t + r * 256;
            int kk = e >> 6;
            int pp = e & 63;
            xs[kk][pp] = xbase[(size_t)(c0 + kk) * HW_ + pp];
        }
        for (int e = t; e < 72 * 16; e += 256) {
            int o  = e >> 4;
            int kk = e & 15;
            ws[o][kk] = w[o * CIN_ + c0 + kk];
        }
        __syncthreads();
#pragma unroll
        for (int kk = 0; kk < 16; kk++) {
            float xv = xs[kk][p];
#pragma unroll
            for (int i = 0; i < 18; i++)
                acc[i] = fmaf(xv, ws[oq * 18 + i][kk], acc[i]);
        }
        __syncthreads();
    }

    float* ob = g_offset + (size_t)(pix0 + p) * OCH_;
#pragma unroll
    for (int i = 0; i < 18; i++) {
        int o = oq * 18 + i;
        ob[o] = acc[i] + bias[o];
    }
}

// ---------------------------------------------------------------------------
// Kernel D: sampler — bilinear gather + bf16 hi/lo split, writes SW128
// swizzled 16KB A-tiles to gmem. grid = (256 pixtiles, 36 chunks), 256 thr.
// ---------------------------------------------------------------------------
__global__ void __launch_bounds__(256) sample_kernel(const float* __restrict__ xt)
{
    __shared__ int   sidx[4*128];
    __shared__ float swgt[4*128];

    const int t  = threadIdx.x;
    const int pb = blockIdx.x;       // pixel tile
    const int gt = blockIdx.y;       // chunk
    const int pix0 = pb * 128;
    const int b    = pix0 >> 14;
    const int hw0  = pix0 & (HW_-1);
    const int hh   = hw0 >> 7;

    const int g   = gt / 9;
    const int tap = gt - 9*g;
    const int ti  = tap / 3;
    const int tj  = tap - 3*ti;
    const int gch = g * 64;

    if (t < 128) {
        const float* op = g_offset + (size_t)(pix0 + t) * OCH_ + gt*2;
        float ys = (float)(hh - 1 + ti) + op[0];
        float xs = (float)(t  - 1 + tj) + op[1];
        float y0f = floorf(ys), x0f = floorf(xs);
        int   y0  = (int)y0f,   x0  = (int)x0f;
        float ly = ys - y0f, lx = xs - x0f;
        float hy = 1.f - ly, hx = 1.f - lx;
        int y1 = y0 + 1, x1 = x0 + 1;
        bool vy0 = (unsigned)y0 < H_, vy1 = (unsigned)y1 < H_;
        bool vx0 = (unsigned)x0 < W_, vx1 = (unsigned)x1 < W_;
        int cy0 = min(max(y0,0),H_-1), cy1 = min(max(y1,0),H_-1);
        int cx0 = min(max(x0,0),W_-1), cx1 = min(max(x1,0),W_-1);
        sidx[0*128 + t] = cy0*W_ + cx0;
        sidx[1*128 + t] = cy0*W_ + cx1;
        sidx[2*128 + t] = cy1*W_ + cx0;
        sidx[3*128 + t] = cy1*W_ + cx1;
        swgt[0*128 + t] = (vy0 && vx0) ? hy*hx : 0.f;
        swgt[1*128 + t] = (vy0 && vx1) ? hy*lx : 0.f;
        swgt[2*128 + t] = (vy1 && vx0) ? ly*hx : 0.f;
        swgt[3*128 + t] = (vy1 && vx1) ? ly*lx : 0.f;
    }
    __syncthreads();

    const float* xb = xt + (size_t)b * HW_ * CIN_;
    const int slot = t & 15;
    const int gp   = t >> 4;

    char* outh = (char*)g_ah + ((size_t)gt*NPB + pb) * 16384;
    char* outl = (char*)g_al + ((size_t)gt*NPB + pb) * 16384;

#pragma unroll
    for (int pass = 0; pass < 8; pass++) {
        const int p  = pass*16 + gp;
        const int i0 = sidx[0*128+p], i1 = sidx[1*128+p];
        const int i2 = sidx[2*128+p], i3 = sidx[3*128+p];
        const float w0 = swgt[0*128+p], w1 = swgt[1*128+p];
        const float w2 = swgt[2*128+p], w3 = swgt[3*128+p];
        const int co = gch + slot*4;
        float4 v0 = *(const float4*)(xb + (size_t)i0*CIN_ + co);
        float4 v1 = *(const float4*)(xb + (size_t)i1*CIN_ + co);
        float4 v2 = *(const float4*)(xb + (size_t)i2*CIN_ + co);
        float4 v3 = *(const float4*)(xb + (size_t)i3*CIN_ + co);
        float r0 = fmaf(w3,v3.x, fmaf(w2,v2.x, fmaf(w1,v1.x, w0*v0.x)));
        float r1 = fmaf(w3,v3.y, fmaf(w2,v2.y, fmaf(w1,v1.y, w0*v0.y)));
        float r2 = fmaf(w3,v3.z, fmaf(w2,v2.z, fmaf(w1,v1.z, w0*v0.z)));
        float r3 = fmaf(w3,v3.w, fmaf(w2,v2.w, fmaf(w1,v1.w, w0*v0.w)));

        __nv_bfloat16 h0 = __float2bfloat16_rn(r0);
        __nv_bfloat16 h1 = __float2bfloat16_rn(r1);
        __nv_bfloat16 h2 = __float2bfloat16_rn(r2);
        __nv_bfloat16 h3 = __float2bfloat16_rn(r3);
        __nv_bfloat16 l0 = __float2bfloat16_rn(r0 - __bfloat162float(h0));
        __nv_bfloat16 l1 = __float2bfloat16_rn(r1 - __bfloat162float(h1));
        __nv_bfloat16 l2 = __float2bfloat16_rn(r2 - __bfloat162float(h2));
        __nv_bfloat16 l3 = __float2bfloat16_rn(r3 - __bfloat162float(h3));

        const uint32_t off = (uint32_t)(p*128 + ((slot*8) ^ ((p & 7) << 4)));
        __nv_bfloat162 hA(h0, h1), hB(h2, h3), lA(l0, l1), lB(l2, l3);
        uint2 hv, lv;
        hv.x = *(uint32_t*)&hA; hv.y = *(uint32_t*)&hB;
        lv.x = *(uint32_t*)&lA; lv.y = *(uint32_t*)&lB;
        *(uint2*)(outh + off) = hv;
        *(uint2*)(outl + off) = lv;
    }
}

// ---------------------------------------------------------------------------
// Kernel E: pure GEMM on HMMA, loads via cp.async.bulk + mbarrier.
// 128 pix x 256 cout per block, 512 threads (16 warps = 4m x 4n, warp 32x64).
// 2-stage pipeline (R7 structure); compute reordered for fragment reuse:
// per k-step 12 LDSM (was 18) — B_hi reused by hi*hi and lo*hi, A_hi reused
// by hi*hi and hi*lo; B array overwritten in place by B_lo to bound regs.
// Stage = Ah 16K | Al 16K | Bh 32K | Bl 32K = 96KB.
// ---------------------------------------------------------------------------
#define GS_AH 0
#define GS_AL 16384
#define GS_BH 32768
#define GS_BL 65536
#define GSTAGE 98304
#define GS_MBAR (2*GSTAGE)          // two 8-byte mbarriers
#define GSMEM (2*GSTAGE + 32)       // 196640

__device__ __forceinline__ void gemm_issue_bulk(uint32_t sbase, uint32_t mbar,
                                                int gt, int pb,
                                                const __nv_bfloat16* wb)
{
    const char* ah = (const char*)g_ah + ((size_t)gt*NPB + pb) * 16384;
    const char* al = (const char*)g_al + ((size_t)gt*NPB + pb) * 16384;
    const char* bs = (const char*)wb + (size_t)gt * 65536;
    mbar_expect_tx(mbar, GSTAGE);
    bulk_copy(sbase + GS_AH, ah, 16384, mbar);
    bulk_copy(sbase + GS_AL, al, 16384, mbar);
    bulk_copy(sbase + GS_BH, bs, 65536, mbar);   // hi+lo contiguous in g_wb
}

__global__ void __launch_bounds__(512, 1)
gemm_kernel(const __nv_bfloat16* __restrict__ wb, float* __restrict__ out)
{
    extern __shared__ char sm[];
    const uint32_t sb = smem_u32(sm);

    const int t = threadIdx.x;
    const int warp = t >> 5, lane = t & 31;
    const int pb   = blockIdx.x;
    const int pix0 = pb * 128;
    const int b    = pix0 >> 14;
    const int hw0  = pix0 & (HW_-1);

    // mbarrier init
    if (t == 0) {
        mbar_init(sb + GS_MBAR, 1);
        mbar_init(sb + GS_MBAR + 8, 1);
    }
    __syncthreads();

    const int wm = warp & 3, wn = warp >> 2;

    const uint32_t rowA = wm*32 + (lane & 15);
    const uint32_t swzA = (rowA & 7) << 4;
    const uint32_t kA   = (uint32_t)(lane & 16);
    const uint32_t aRow = rowA * 128;

    const uint32_t rowB = wn*64 + (lane & 7) + ((lane & 16) >> 1);
    const uint32_t swzB = (rowB & 7) << 4;
    const uint32_t kB   = (uint32_t)((lane & 8) << 1);
    const uint32_t bRow = rowB * 128;

    float acc[2][8][4];
#pragma unroll
    for (int i = 0; i < 2; i++)
#pragma unroll
        for (int j = 0; j < 8; j++)
#pragma unroll
            for (int q = 0; q < 4; q++) acc[i][j][q] = 0.f;

    if (t == 0) gemm_issue_bulk(sb, sb + GS_MBAR, 0, pb, wb);

    for (int gt = 0; gt < NCHUNK; gt++) {
        const int s = gt & 1;
        const uint32_t cur = sb + s * GSTAGE;
        if (gt + 1 < NCHUNK && t == 0)
            gemm_issue_bulk(sb + ((gt + 1) & 1) * GSTAGE,
                            sb + GS_MBAR + ((gt + 1) & 1) * 8, gt + 1, pb, wb);

        mbar_wait(sb + GS_MBAR + s * 8, (gt >> 1) & 1);

        // 4 k-steps; fragment-reuse order: hi*hi -> lo*hi -> hi*lo
#pragma unroll
        for (int ks = 0; ks < 4; ks++) {
            const uint32_t kbyte = (uint32_t)(ks * 32);
            const uint32_t aoff = (kbyte + kA) ^ swzA;
            const uint32_t boff = (kbyte + kB) ^ swzB;

            uint32_t bfr[4][4], ah[2][4], al[2][4];

            // load B_hi + A_hi
#pragma unroll
            for (int np = 0; np < 4; np++)
                ldsm_x4(bfr[np], cur + GS_BH + bRow + np*2048 + boff);
#pragma unroll
            for (int mt = 0; mt < 2; mt++)
                ldsm_x4(ah[mt], cur + GS_AH + aRow + mt*2048 + aoff);

            // hi * hi
#pragma unroll
            for (int mt = 0; mt < 2; mt++)
#pragma unroll
                for (int nt = 0; nt < 8; nt++)
                    mma_bf16(acc[mt][nt], ah[mt],
                             bfr[nt >> 1][(nt & 1) * 2],
                             bfr[nt >> 1][(nt & 1) * 2 + 1]);

            // load A_lo, lo * hi (reuse B_hi)
#pragma unroll
            for (int mt = 0; mt < 2; mt++)
                ldsm_x4(al[mt], cur + GS_AL + aRow + mt*2048 + aoff);
#pragma unroll
            for (int mt = 0; mt < 2; mt++)
#pragma unroll
                for (int nt = 0; nt < 8; nt++)
                    mma_bf16(acc[mt][nt], al[mt],
                             bfr[nt >> 1][(nt & 1) * 2],
                             bfr[nt >> 1][(nt & 1) * 2 + 1]);

            // load B_lo in place, hi * lo (reuse A_hi)
#pragma unroll
            for (int np = 0; np < 4; np++)
                ldsm_x4(bfr[np], cur + GS_BL + bRow + np*2048 + boff);
#pragma unroll
            for (int mt = 0; mt < 2; mt++)
#pragma unroll
                for (int nt = 0; nt < 8; nt++)
                    mma_bf16(acc[mt][nt], ah[mt],
                             bfr[nt >> 1][(nt & 1) * 2],
                             bfr[nt >> 1][(nt & 1) * 2 + 1]);
        }
        __syncthreads();   // all warps done reading stage s before refill
    }

    // ---- epilogue: relu + store (NCHW) ----
    const size_t ob = (size_t)b * COUT_ * HW_ + hw0;
    const int mrow = wm*32 + (lane >> 2);
    const int ncol = wn*64 + (lane & 3) * 2;
#pragma unroll
    for (int mt = 0; mt < 2; mt++) {
#pragma unroll
        for (int nt = 0; nt < 8; nt++) {
            const int m = mrow + mt*16;
            const int n = ncol + nt*8;
            float* o0 = out + ob + (size_t)n * HW_ + m;
            o0[0]        = fmaxf(acc[mt][nt][0], 0.f);
            o0[HW_]      = fmaxf(acc[mt][nt][1], 0.f);
            o0[8]        = fmaxf(acc[mt][nt][2], 0.f);
            o0[HW_ + 8]  = fmaxf(acc[mt][nt][3], 0.f);
        }
    }
}

// ---------------------------------------------------------------------------
extern "C" void kernel_launch(void* const* d_in, const int* in_sizes, int n_in,
                              void* d_out, int out_size)
{
    (void)in_sizes; (void)n_in; (void)out_size;
    const float* x     = (const float*)d_in[0];
    const float* w_off = (const float*)d_in[1];
    const float* b_off = (const float*)d_in[2];
    const float* w_def = (const float*)d_in[3];
    float* out = (float*)d_out;

    float* xt;           cudaGetSymbolAddress((void**)&xt, g_xt);
    __nv_bfloat16* wbp;  cudaGetSymbolAddress((void**)&wbp, g_wb);

    transpose_kernel<<<dim3(HW_/32, CIN_/32, B_), dim3(32, 8)>>>(x, xt);
    prepack_kernel<<<NCHUNK, 256>>>(w_def, wbp);
    offset_kernel<<<B_*HW_/64, 256>>>(x, w_off, b_off);
    sample_kernel<<<dim3(NPB, NCHUNK), 256>>>(xt);

    static bool attr_set = false;
    if (!attr_set) {
        cudaFuncSetAttribute(gemm_kernel,
                             cudaFuncAttributeMaxDynamicSharedMemorySize, GSMEM);
        attr_set = true;
    }
    gemm_kernel<<<NPB, 512, GSMEM>>>(wbp, out);
}